// round 6
// baseline (speedup 1.0000x reference)
#include <cuda_runtime.h>
#include <cstdint>

// AnchorLoss: sum over masked pairs of 1 - exp(-||p_i - p_j||^2 / 10).
// p = embedding + abs_coords, B=8, N=2048, D=2.
//
// Shape: 2 i-rows per warp (reuse each smem point load for both rows,
// 2 independent mask LDG.128 per iter), j-dim split in half per block so
// the point cache is 8 KB -> 8 blocks/SM, 64 resident warps, single wave
// (2048 blocks). Points pre-scaled by sqrt(log2(e)/10) so
// exp(-d^2/10) = ex2(-(dx'^2+dy'^2)) with the sign folded into FFMA.

constexpr int BDIM = 8;
constexpr int NDIM = 2048;
constexpr int JH = NDIM / 2;          // 1024 j per block
constexpr int WARPS = 8;
constexpr int THREADS = WARPS * 32;   // 256
constexpr int ROWS_BLK = WARPS * 2;   // 16 i-rows per block
constexpr int GRID_X = NDIM / ROWS_BLK;          // 128
constexpr int NBLOCKS = GRID_X * 2 * BDIM;       // 2048
constexpr int NITER = JH / 128;                  // 8 int4-columns per lane

__device__ float g_partial[NBLOCKS];
__device__ unsigned int g_count = 0;

__device__ __forceinline__ float ex2_approx(float x) {
    float r;
    asm("ex2.approx.ftz.f32 %0, %1;" : "=f"(r) : "f"(x));
    return r;
}

__global__ void __launch_bounds__(THREADS, 8)
anchor_fused(const float* __restrict__ emb,
             const float* __restrict__ coords,
             const int*   __restrict__ mask,
             float*       __restrict__ out) {
    __shared__ float2 sp[JH];     // scaled points for this j-half (8 KB)
    __shared__ float wsum[WARPS];
    __shared__ unsigned s_ticket;

    constexpr float SC = 0.37982825319573816f;  // sqrt(log2(e)/10)

    const int b  = blockIdx.z;
    const int jh = blockIdx.y;              // 0 or 1: j-half
    const int j0 = jh * JH;

    const float2* e2 = reinterpret_cast<const float2*>(emb    + (size_t)b * NDIM * 2);
    const float2* c2 = reinterpret_cast<const float2*>(coords + (size_t)b * NDIM * 2);

    for (int t = threadIdx.x; t < JH; t += THREADS) {
        float2 e = e2[j0 + t];
        float2 c = c2[j0 + t];
        sp[t] = make_float2(SC * (e.x + c.x), SC * (e.y + c.y));
    }
    __syncthreads();

    const int warp = threadIdx.x >> 5;
    const int lane = threadIdx.x & 31;
    const int i0 = blockIdx.x * ROWS_BLK + warp * 2;
    const int i1 = i0 + 1;

    // scaled row points (global, L2-hit broadcast; i may be outside j-half)
    float2 ea = e2[i0], ca = c2[i0];
    float2 eb = e2[i1], cb = c2[i1];
    const float pax = SC * (ea.x + ca.x), pay = SC * (ea.y + ca.y);
    const float pbx = SC * (eb.x + cb.x), pby = SC * (eb.y + cb.y);

    const int4* mrow0 = reinterpret_cast<const int4*>(
        mask + ((size_t)b * NDIM + (size_t)i0) * NDIM + j0);
    const int4* mrow1 = reinterpret_cast<const int4*>(
        mask + ((size_t)b * NDIM + (size_t)i1) * NDIM + j0);
    const float4* spv = reinterpret_cast<const float4*>(sp);

    float accA = 0.0f, accB = 0.0f;
    int   cntA = 0,    cntB = 0;

#pragma unroll 2
    for (int it = 0; it < NITER; ++it) {
        const int a = it * 32 + lane;       // int4 index within the half
        const int4 m0 = __ldcs(&mrow0[a]);  // row i0 masks, j = 4a..4a+3
        const int4 m1 = __ldcs(&mrow1[a]);  // row i1 masks

        const float4 v01 = spv[2 * a + 0];  // points 4a, 4a+1
        const float4 v23 = spv[2 * a + 1];  // points 4a+2, 4a+3

#define PAIR(px_, py_, mc0, mc1)                                           \
        {                                                                  \
            float dxA = pax - (px_), dyA = pay - (py_);                    \
            float dxB = pbx - (px_), dyB = pby - (py_);                    \
            float tA = -dxA * dxA, tB = -dxB * dxB;                        \
            float eA = ex2_approx(fmaf(-dyA, dyA, tA));                    \
            float eB = ex2_approx(fmaf(-dyB, dyB, tB));                    \
            accA += __int_as_float(__float_as_int(eA) & -(mc0));           \
            accB += __int_as_float(__float_as_int(eB) & -(mc1));           \
            cntA += (mc0);                                                 \
            cntB += (mc1);                                                 \
        }
        PAIR(v01.x, v01.y, m0.x, m1.x)
        PAIR(v01.z, v01.w, m0.y, m1.y)
        PAIR(v23.x, v23.y, m0.z, m1.z)
        PAIR(v23.z, v23.w, m0.w, m1.w)
#undef PAIR
    }

    float val = ((float)cntA - accA) + ((float)cntB - accB);

    // warp reduce
#pragma unroll
    for (int off = 16; off; off >>= 1)
        val += __shfl_xor_sync(0xffffffffu, val, off);

    if (lane == 0) wsum[warp] = val;
    __syncthreads();

    if (threadIdx.x == 0) {
        float s = 0.0f;
#pragma unroll
        for (int w = 0; w < WARPS; ++w) s += wsum[w];
        g_partial[(blockIdx.z * 2 + blockIdx.y) * GRID_X + blockIdx.x] = s;
        __threadfence();
        s_ticket = atomicAdd(&g_count, 1u);
    }
    __syncthreads();

    // Last block performs the deterministic final reduction.
    if (s_ticket == NBLOCKS - 1) {
        __threadfence();  // make all g_partial writes visible
        double* sd = reinterpret_cast<double*>(sp);  // reuse smem (2 KB of 8)
        double acc = 0.0;
        for (int idx = threadIdx.x; idx < NBLOCKS; idx += THREADS)
            acc += (double)g_partial[idx];
        sd[threadIdx.x] = acc;
        __syncthreads();
#pragma unroll
        for (int off = THREADS / 2; off; off >>= 1) {
            if (threadIdx.x < off) sd[threadIdx.x] += sd[threadIdx.x + off];
            __syncthreads();
        }
        if (threadIdx.x == 0) {
            out[0] = (float)sd[0];
            g_count = 0;   // reset for next graph replay
        }
    }
}

extern "C" void kernel_launch(void* const* d_in, const int* in_sizes, int n_in,
                              void* d_out, int out_size) {
    const float* emb    = (const float*)d_in[0];
    const float* coords = (const float*)d_in[1];
    const int*   mask   = (const int*)d_in[2];
    float* out = (float*)d_out;

    dim3 grid(GRID_X, 2, BDIM);
    anchor_fused<<<grid, THREADS>>>(emb, coords, mask, out);
}

// round 7
// speedup vs baseline: 1.0445x; 1.0445x over previous
#include <cuda_runtime.h>
#include <cstdint>

// AnchorLoss: sum over masked pairs of 1 - exp(-||p_i - p_j||^2 / 10).
// p = embedding + abs_coords, B=8, N=2048, D=2.
//
// Issue-bound => minimize instructions/pair:
//  - packed f32x2 math: one add/mul/fma computes BOTH i-rows of a warp
//  - smem point table stores {-sx,-sx,-sy,-sy} (SC-prescaled, negated,
//    duplicated) transposed by 4 -> conflict-free LDS.128
//  - gate with I2F+FFMA (I2FP is cheap alu-class), count via IADD3 folding
// Shape: 2 i-rows/warp, half-j per block, 2048 blocks, 56 warps/SM.

constexpr int BDIM = 8;
constexpr int NDIM = 2048;
constexpr int JH = NDIM / 2;          // 1024 j per block
constexpr int WARPS = 8;
constexpr int THREADS = WARPS * 32;   // 256
constexpr int ROWS_BLK = WARPS * 2;   // 16 i-rows per block
constexpr int GRID_X = NDIM / ROWS_BLK;          // 128
constexpr int NBLOCKS = GRID_X * 2 * BDIM;       // 2048
constexpr int NITER = JH / 128;                  // 8 int4-columns per lane
constexpr int Q4 = JH / 4;                       // 256 (transposed stride)

__device__ float g_partial[NBLOCKS];
__device__ unsigned int g_count = 0;

__device__ __forceinline__ float ex2_approx(float x) {
    float r;
    asm("ex2.approx.ftz.f32 %0, %1;" : "=f"(r) : "f"(x));
    return r;
}
__device__ __forceinline__ unsigned long long f2_add(unsigned long long a, unsigned long long b) {
    unsigned long long d;
    asm("add.rn.f32x2 %0, %1, %2;" : "=l"(d) : "l"(a), "l"(b));
    return d;
}
__device__ __forceinline__ unsigned long long f2_mul(unsigned long long a, unsigned long long b) {
    unsigned long long d;
    asm("mul.rn.f32x2 %0, %1, %2;" : "=l"(d) : "l"(a), "l"(b));
    return d;
}
__device__ __forceinline__ unsigned long long f2_fma(unsigned long long a, unsigned long long b,
                                                     unsigned long long c) {
    unsigned long long d;
    asm("fma.rn.f32x2 %0, %1, %2, %3;" : "=l"(d) : "l"(a), "l"(b), "l"(c));
    return d;
}
__device__ __forceinline__ unsigned long long f2_pack(float lo, float hi) {
    unsigned long long d;
    asm("mov.b64 %0, {%1, %2};" : "=l"(d) : "f"(lo), "f"(hi));
    return d;
}
__device__ __forceinline__ void f2_unpack(unsigned long long v, float& lo, float& hi) {
    asm("mov.b64 {%0, %1}, %2;" : "=f"(lo), "=f"(hi) : "l"(v));
}

__global__ void __launch_bounds__(THREADS, 7)
anchor_fused(const float* __restrict__ emb,
             const float* __restrict__ coords,
             const int*   __restrict__ mask,
             float*       __restrict__ out) {
    // sq[(j&3)*Q4 + (j>>2)] = {-sx,-sx,-sy,-sy} for point j of this half (16 KB)
    __shared__ float4 sq[JH];
    __shared__ float wsum[WARPS];
    __shared__ unsigned s_ticket;

    constexpr float SC = 0.37982825319573816f;  // sqrt(log2(e)/10)
    constexpr unsigned long long NEG1X2 = 0xBF800000BF800000ULL;  // {-1.f,-1.f}

    const int b  = blockIdx.z;
    const int j0 = blockIdx.y * JH;     // j-half origin

    const float2* e2 = reinterpret_cast<const float2*>(emb    + (size_t)b * NDIM * 2);
    const float2* c2 = reinterpret_cast<const float2*>(coords + (size_t)b * NDIM * 2);

    for (int t = threadIdx.x; t < JH; t += THREADS) {
        float2 e = e2[j0 + t];
        float2 c = c2[j0 + t];
        float nx = -SC * (e.x + c.x), ny = -SC * (e.y + c.y);
        sq[(t & 3) * Q4 + (t >> 2)] = make_float4(nx, nx, ny, ny);
    }
    __syncthreads();

    const int warp = threadIdx.x >> 5;
    const int lane = threadIdx.x & 31;
    const int i0 = blockIdx.x * ROWS_BLK + warp * 2;
    const int i1 = i0 + 1;

    float2 ea = e2[i0], ca = c2[i0];
    float2 eb = e2[i1], cb = c2[i1];
    const unsigned long long ppx = f2_pack(SC * (ea.x + ca.x), SC * (eb.x + cb.x));
    const unsigned long long ppy = f2_pack(SC * (ea.y + ca.y), SC * (eb.y + cb.y));

    const int4* mrow0 = reinterpret_cast<const int4*>(
        mask + ((size_t)b * NDIM + (size_t)i0) * NDIM + j0);
    const int4* mrow1 = reinterpret_cast<const int4*>(
        mask + ((size_t)b * NDIM + (size_t)i1) * NDIM + j0);
    const ulonglong2* sqv = reinterpret_cast<const ulonglong2*>(sq);

    float accA = 0.0f, accB = 0.0f;
    int   cntA = 0,    cntB = 0;

#pragma unroll 2
    for (int it = 0; it < NITER; ++it) {
        const int a = it * 32 + lane;       // column group within the half
        const int4 m0 = __ldcs(&mrow0[a]);  // row i0 masks, j = 4a..4a+3
        const int4 m1 = __ldcs(&mrow1[a]);  // row i1 masks

#define PAIR(k, mA, mB)                                                        \
        {                                                                      \
            const ulonglong2 v = sqv[(k) * Q4 + a];   /* LDS.128, no conflict */\
            unsigned long long dx = f2_add(ppx, v.x); /* both rows at once  */ \
            unsigned long long dy = f2_add(ppy, v.y);                          \
            unsigned long long t  = f2_mul(dx, dx);                            \
            unsigned long long s  = f2_fma(dy, dy, t);                         \
            unsigned long long ns = f2_mul(s, NEG1X2);                         \
            float nsA, nsB;                                                    \
            f2_unpack(ns, nsA, nsB);                                           \
            accA = fmaf((float)(mA), ex2_approx(nsA), accA);                   \
            accB = fmaf((float)(mB), ex2_approx(nsB), accB);                   \
        }
        PAIR(0, m0.x, m1.x)
        PAIR(1, m0.y, m1.y)
        PAIR(2, m0.z, m1.z)
        PAIR(3, m0.w, m1.w)
#undef PAIR
        cntA += m0.x + m0.y;  cntA += m0.z + m0.w;   // IADD3-foldable
        cntB += m1.x + m1.y;  cntB += m1.z + m1.w;
    }

    float val = ((float)cntA - accA) + ((float)cntB - accB);

    // warp reduce
#pragma unroll
    for (int off = 16; off; off >>= 1)
        val += __shfl_xor_sync(0xffffffffu, val, off);

    if (lane == 0) wsum[warp] = val;
    __syncthreads();

    if (threadIdx.x == 0) {
        float s = 0.0f;
#pragma unroll
        for (int w = 0; w < WARPS; ++w) s += wsum[w];
        g_partial[(blockIdx.z * 2 + blockIdx.y) * GRID_X + blockIdx.x] = s;
        __threadfence();
        s_ticket = atomicAdd(&g_count, 1u);
    }
    __syncthreads();

    // Last block performs the deterministic final reduction.
    if (s_ticket == NBLOCKS - 1) {
        __threadfence();  // make all g_partial writes visible
        double* sd = reinterpret_cast<double*>(sq);  // reuse smem
        double acc = 0.0;
        for (int idx = threadIdx.x; idx < NBLOCKS; idx += THREADS)
            acc += (double)g_partial[idx];
        sd[threadIdx.x] = acc;
        __syncthreads();
#pragma unroll
        for (int off = THREADS / 2; off; off >>= 1) {
            if (threadIdx.x < off) sd[threadIdx.x] += sd[threadIdx.x + off];
            __syncthreads();
        }
        if (threadIdx.x == 0) {
            out[0] = (float)sd[0];
            g_count = 0;   // reset for next graph replay
        }
    }
}

extern "C" void kernel_launch(void* const* d_in, const int* in_sizes, int n_in,
                              void* d_out, int out_size) {
    const float* emb    = (const float*)d_in[0];
    const float* coords = (const float*)d_in[1];
    const int*   mask   = (const int*)d_in[2];
    float* out = (float*)d_out;

    dim3 grid(GRID_X, 2, BDIM);
    anchor_fused<<<grid, THREADS>>>(emb, coords, mask, out);
}